// round 16
// baseline (speedup 1.0000x reference)
#include <cuda_runtime.h>
#include <cuda_fp16.h>
#include <math.h>
#include <stdint.h>

// Problem dims (fixed by setup_inputs): x [4,4096,2048] fp32, W [2048,2048] fp32
#define M_DIM 16384
#define K_DIM 2048
#define N_DIM 2048

static const long long NELEM = (long long)M_DIM * (long long)K_DIM;

// Scratch (no alloc allowed)
__device__ __half g_xsp_c[M_DIM * K_DIM / 2];          // compressed 2:4 A (32 MB)
// metadata, fm-vectorized layout:
// u16 idx = mcta*16384 + kt*1024 + g*512 + s*128 + eQ*64 + gr*8 + fm*2 + hi
// (mcta=row>>7, g=(row>>6)&1, fm=(row>>4)&3, hi=(row>>3)&1, gr=row&7;
//  kt=c>>3, s=(c>>1)&3, eQ=c&1; c = k16 chunk index 0..127)
__device__ uint16_t g_meta[M_DIM * K_DIM / 16];        // 4 MB
__device__ __half g_wh[N_DIM * K_DIM];                 // W in fp16 (8 MB)
__device__ double g_sums[4];

// ---------------------------------------------------------------------------
// Kernel 1 (merged): blocks [0,2048): 2:4 prune -> compressed vals + repacked
// metadata + moments.  blocks [2048,3072): convert W to fp16.
// ---------------------------------------------------------------------------
#define PRUNE_BLOCKS 2048
#define WCONV_BLOCKS 1024

__global__ void prep_kernel(const float* __restrict__ x, const float* __restrict__ W) {
    if (blockIdx.x >= PRUNE_BLOCKS) {
        // ---- W conversion branch ----
        const int bid = blockIdx.x - PRUNE_BLOCKS;
        const int nq = N_DIM * K_DIM / 4;                 // 1048576 float4
        __half2* y = (__half2*)g_wh;
        for (int i = bid * blockDim.x + threadIdx.x; i < nq;
             i += WCONV_BLOCKS * blockDim.x) {
            float4 w4 = ((const float4*)W)[i];
            y[2 * i]     = __floats2half2_rn(w4.x, w4.y);
            y[2 * i + 1] = __floats2half2_rn(w4.z, w4.w);
        }
        return;
    }

    // ---- prune branch ----
    const long long nb = NELEM / 16;                      // (row, chunk) pairs
    float s0 = 0.f, s1 = 0.f, s2 = 0.f, s3 = 0.f;

    const long long stride = (long long)PRUNE_BLOCKS * blockDim.x;
    for (long long b = (long long)blockIdx.x * blockDim.x + threadIdx.x;
         b < nb; b += stride) {
        const float4* xp = (const float4*)x + b * 4;
        uint32_t packed[4];
        uint32_t meta = 0;
#pragma unroll
        for (int g = 0; g < 4; g++) {
            float4 v = xp[g];
            float e[4] = {v.x, v.y, v.z, v.w};
            float a[4] = {fabsf(v.x), fabsf(v.y), fabsf(v.z), fabsf(v.w)};
            int k0 = -1, k1 = -1;
#pragma unroll
            for (int i = 0; i < 4; i++) {
                int beats = 0;
#pragma unroll
                for (int j = 0; j < 4; j++) {
                    if (j == i) continue;
                    beats += (a[j] > a[i]) || (a[j] == a[i] && j < i);
                }
                if (beats < 2) { if (k0 < 0) k0 = i; else k1 = i; }
            }
            const float v0 = e[k0], v1 = e[k1];
            s0 += e[0] + e[1] + e[2] + e[3];
            s1 += e[0]*e[0] + e[1]*e[1] + e[2]*e[2] + e[3]*e[3];
            s2 += v0 + v1;
            s3 += v0 * v0 + v1 * v1;
            __half2 h = __floats2half2_rn(v0, v1);
            packed[g] = *(uint32_t*)&h;
            meta |= (uint32_t)(k0 | (k1 << 2)) << (4 * g);
        }
        ((uint4*)g_xsp_c)[b] = make_uint4(packed[0], packed[1], packed[2], packed[3]);

        // fm-vectorized metadata store (see layout comment at g_meta)
        const int row = (int)(b >> 7);          // K/16 = 128 chunks per row
        const int c = (int)(b & 127);
        const int mcta = row >> 7;
        const int gg = (row >> 6) & 1;
        const int fm = (row >> 4) & 3;
        const int hi = (row >> 3) & 1;
        const int gr = row & 7;
        const int kt = c >> 3;
        const int s = (c >> 1) & 3;
        const int eQ = c & 1;
        g_meta[mcta * 16384 + kt * 1024 + gg * 512 + s * 128 + eQ * 64 +
               gr * 8 + fm * 2 + hi] = (uint16_t)meta;
    }

#pragma unroll
    for (int off = 16; off > 0; off >>= 1) {
        s0 += __shfl_down_sync(0xffffffffu, s0, off);
        s1 += __shfl_down_sync(0xffffffffu, s1, off);
        s2 += __shfl_down_sync(0xffffffffu, s2, off);
        s3 += __shfl_down_sync(0xffffffffu, s3, off);
    }
    __shared__ float red[4][8];
    int lane = threadIdx.x & 31;
    int w = threadIdx.x >> 5;
    if (lane == 0) {
        red[0][w] = s0; red[1][w] = s1; red[2][w] = s2; red[3][w] = s3;
    }
    __syncthreads();
    if (threadIdx.x == 0) {
        float t0 = 0.f, t1 = 0.f, t2 = 0.f, t3 = 0.f;
        int nw = (blockDim.x + 31) >> 5;
        for (int i = 0; i < nw; i++) {
            t0 += red[0][i]; t1 += red[1][i]; t2 += red[2][i]; t3 += red[3][i];
        }
        atomicAdd(&g_sums[0], (double)t0);
        atomicAdd(&g_sums[1], (double)t1);
        atomicAdd(&g_sums[2], (double)t2);
        atomicAdd(&g_sums[3], (double)t3);
    }
}

// ---------------------------------------------------------------------------
// Kernel 2: sparse fp16 GEMM  out[m][n] = v * sum_k x_sp[m][k] * W[n][k]
// mma.sp::ordered_metadata.m16n8k32. BM=BN=128, BKS=128 per K-tile,
// double-buffered cp.async, 8 warps (2x4), warp tile 64x32.
// Lean loader (base+immediate). Metadata: one LDS.128 per s-step.
// ---------------------------------------------------------------------------
#define BM 128
#define BN 128
#define BKS 128                        // source K per tile
#define NITER (K_DIM / BKS)            // 16

#define A_STG_B (BM * 128)             // compressed A: 128B/row -> 16 KB
#define B_STG_B (BN * 256)             // dense B: 256B/row -> 32 KB
#define M_STG_B 2048                   // meta: 2 KB contiguous per ktile
#define STG_B (A_STG_B + B_STG_B + M_STG_B)
#define SMEM_DYN (2 * STG_B + 1024)

static __device__ __forceinline__ uint32_t smem_u32(const void* p) {
    uint32_t a;
    asm("{ .reg .u64 t; cvta.to.shared.u64 t, %1; cvt.u32.u64 %0, t; }" : "=r"(a) : "l"(p));
    return a;
}

#define CP_ASYNC16(dst, src) \
    asm volatile("cp.async.cg.shared.global [%0], [%1], 16;" :: "r"(dst), "l"(src) : "memory")
#define CP_COMMIT() asm volatile("cp.async.commit_group;" ::: "memory")
#define CP_WAIT1()  asm volatile("cp.async.wait_group 1;" ::: "memory")
#define CP_WAIT0()  asm volatile("cp.async.wait_group 0;" ::: "memory")

#define LDSM_X4(r0, r1, r2, r3, addr) \
    asm volatile("ldmatrix.sync.aligned.m8n8.x4.shared.b16 {%0,%1,%2,%3}, [%4];" \
        : "=r"(r0), "=r"(r1), "=r"(r2), "=r"(r3) : "r"(addr))

static __device__ __forceinline__ void mma_sp(
    float* c, const uint32_t* a,
    uint32_t b0, uint32_t b1, uint32_t b2, uint32_t b3, uint32_t e) {
    asm volatile(
        "mma.sp::ordered_metadata.sync.aligned.m16n8k32.row.col.f32.f16.f16.f32 "
        "{%0,%1,%2,%3}, {%4,%5,%6,%7}, {%8,%9,%10,%11}, {%0,%1,%2,%3}, %12, 0x0;"
        : "+f"(c[0]), "+f"(c[1]), "+f"(c[2]), "+f"(c[3])
        : "r"(a[0]), "r"(a[1]), "r"(a[2]), "r"(a[3]),
          "r"(b0), "r"(b1), "r"(b2), "r"(b3), "r"(e));
}

__global__ __launch_bounds__(256, 2)
void gemm_sp_kernel(float* __restrict__ out) {
    extern __shared__ char smem[];

    const int tid = threadIdx.x;
    const int wid = tid >> 5;
    const int lane = tid & 31;
    const int bm = blockIdx.y * BM;
    const int bn = blockIdx.x * BN;

    const uint32_t tile_base = (smem_u32(smem) + 1023u) & ~1023u;

    // ---- loader bases (chunk index only shifts row by multiples of 8, so
    //      row&7, c, and the swizzle XOR are all chunk-invariant) ------------
    // A: row0 = tid>>3, c = tid&7; chunk i -> row += 32 (src +64KB, dst +4KB)
    const char* aSrc = (const char*)g_xsp_c + (size_t)bm * 2048 +
                       (size_t)(tid >> 3) * 2048 + (tid & 7) * 16;
    const uint32_t aDst = (uint32_t)((tid >> 3) * 128 +
                          (((tid & 7) ^ ((tid >> 3) & 7)) << 4));
    // B: row0 = tid>>4, c = tid&15; chunk i -> row += 16 (src +64KB, dst +4KB)
    const char* bSrc = (const char*)g_wh + (size_t)bn * 4096 +
                       (size_t)(tid >> 4) * 4096 + (tid & 15) * 16;
    const uint32_t bDst = (uint32_t)(A_STG_B + (tid >> 4) * 256 +
                          ((((tid & 15) & 8) | (((tid & 15) ^ (tid >> 4)) & 7)) << 4));
    // meta: 2 KB contiguous per ktile (first 128 threads, 16B each)
    const char* mSrc = (const char*)g_meta + (size_t)(bm >> 7) * 32768 + tid * 16;
    const uint32_t mDst = (uint32_t)(A_STG_B + B_STG_B + tid * 16);

    auto load_stage = [&](int buf, int kt) {
        const uint32_t base = tile_base + buf * STG_B;
        const int ka = kt * 128;                // A byte offset along K
        const int kb = kt * 256;                // B byte offset along K
#pragma unroll
        for (int i = 0; i < 4; i++)
            CP_ASYNC16(base + aDst + i * 4096, aSrc + ka + i * 65536);
#pragma unroll
        for (int i = 0; i < 8; i++)
            CP_ASYNC16(base + bDst + i * 4096, bSrc + kb + i * 65536);
        if (tid < 128)
            CP_ASYNC16(base + mDst, mSrc + kt * 2048);
    };

    load_stage(0, 0);
    CP_COMMIT();

    const int mw = (wid >> 2) * 64;     // warp M offset
    const int nw = (wid & 3) * 32;      // warp N offset
    const int gr = lane >> 2;
    const int tg = lane & 3;

    float acc[4][4][4];
#pragma unroll
    for (int i = 0; i < 4; i++)
#pragma unroll
        for (int j = 0; j < 4; j++)
#pragma unroll
            for (int q = 0; q < 4; q++) acc[i][j][q] = 0.f;

    // precomputed fragment addressing
    const int aRow = lane & 15;                 // within 16-row block
    const int aKc = lane >> 4;                  // chunk parity
    const int bRow = ((lane >> 4) << 3) + (lane & 7);
    const int bKc = (lane >> 3) & 1;
    const int eQ = lane & 1;                    // metadata chunk parity
    // metadata base within stage: g = mw>>6, + eQ*128 + gr*16
    const uint32_t mInv = (uint32_t)(A_STG_B + B_STG_B +
                                     (mw >> 6) * 1024 + eQ * 128 + gr * 16);

    for (int kt = 0; kt < NITER; kt++) {
        if (kt + 1 < NITER) {
            load_stage((kt + 1) & 1, kt + 1);
            CP_COMMIT();
            CP_WAIT1();
        } else {
            CP_WAIT0();
        }
        __syncthreads();

        const uint32_t sA = tile_base + (kt & 1) * STG_B;
        const uint32_t sB = sA + A_STG_B;
        const uint32_t mBase = sA + mInv - A_STG_B + A_STG_B;  // = sA offset + mInv rel
        const uint32_t mAddr0 = tile_base + (kt & 1) * STG_B + mInv;

#pragma unroll
        for (int s = 0; s < 4; s++) {           // 4 x k32 steps (compressed k16)
            uint32_t a[4][4];
#pragma unroll
            for (int fm = 0; fm < 4; fm++) {
                const int row = mw + fm * 16 + aRow;
                const int c = s * 2 + aKc;
                LDSM_X4(a[fm][0], a[fm][1], a[fm][2], a[fm][3],
                        sA + row * 128 + ((uint32_t)(c ^ (row & 7)) << 4));
            }
            uint32_t bf[2][2][4];               // [pr][khalf][reg]
#pragma unroll
            for (int pr = 0; pr < 2; pr++)
#pragma unroll
                for (int h = 0; h < 2; h++) {
                    const int row = nw + pr * 16 + bRow;
                    const int c = s * 4 + h * 2 + bKc;
                    const uint32_t swc = (uint32_t)((c & 8) | ((c ^ row) & 7));
                    LDSM_X4(bf[pr][h][0], bf[pr][h][1], bf[pr][h][2], bf[pr][h][3],
                            sB + row * 256 + (swc << 4));
                }
            // metadata: one LDS.128 -> ee[fm=0..3] for this s-step
            uint32_t ee[4];
            asm volatile("ld.shared.v4.u32 {%0,%1,%2,%3}, [%4];"
                : "=r"(ee[0]), "=r"(ee[1]), "=r"(ee[2]), "=r"(ee[3])
                : "r"(mAddr0 + (uint32_t)(s * 256)));
#pragma unroll
            for (int fm = 0; fm < 4; fm++)
#pragma unroll
                for (int fn = 0; fn < 4; fn++)
                    mma_sp(acc[fm][fn], a[fm],
                           bf[fn >> 1][0][(fn & 1) * 2], bf[fn >> 1][0][(fn & 1) * 2 + 1],
                           bf[fn >> 1][1][(fn & 1) * 2], bf[fn >> 1][1][(fn & 1) * 2 + 1],
                           ee[fm]);
        }
        __syncthreads();
    }

    // ---- epilogue: compute v from moments, scale + store --------------------
    const double n = (double)NELEM;
    const double var_x  = (g_sums[1] - g_sums[0] * g_sums[0] / n) / (n - 1.0);
    double var_sp = (g_sums[3] - g_sums[2] * g_sums[2] / n) / (n - 1.0);
    if (var_sp < 1e-9) var_sp = 1e-9;
    const float v = (float)sqrt(var_x / var_sp);

#pragma unroll
    for (int fm = 0; fm < 4; fm++) {
        const int r0 = bm + mw + fm * 16 + gr;
        const int r1 = r0 + 8;
#pragma unroll
        for (int fn = 0; fn < 4; fn++) {
            const int c = bn + nw + fn * 8 + tg * 2;
            *(float2*)&out[(size_t)r0 * N_DIM + c] =
                make_float2(v * acc[fm][fn][0], v * acc[fm][fn][1]);
            *(float2*)&out[(size_t)r1 * N_DIM + c] =
                make_float2(v * acc[fm][fn][2], v * acc[fm][fn][3]);
        }
    }
}

// ---------------------------------------------------------------------------
// Entry point
// ---------------------------------------------------------------------------
extern "C" void kernel_launch(void* const* d_in, const int* in_sizes, int n_in,
                              void* d_out, int out_size) {
    const float* x = (const float*)d_in[0];
    const float* w = (const float*)d_in[1];
    float* out = (float*)d_out;

    // zero the moment accumulators via a graph-capturable memset node
    void* sums_addr = 0;
    cudaGetSymbolAddress(&sums_addr, g_sums);
    cudaMemsetAsync(sums_addr, 0, 4 * sizeof(double));

    prep_kernel<<<PRUNE_BLOCKS + WCONV_BLOCKS, 256>>>(x, w);

    cudaFuncSetAttribute(gemm_sp_kernel,
                         cudaFuncAttributeMaxDynamicSharedMemorySize, SMEM_DYN);
    dim3 grid(N_DIM / BN, M_DIM / BM);
    gemm_sp_kernel<<<grid, 256, SMEM_DYN>>>(out);
}

// round 17
// speedup vs baseline: 1.0143x; 1.0143x over previous
#include <cuda_runtime.h>
#include <cuda_fp16.h>
#include <math.h>
#include <stdint.h>

// Problem dims (fixed by setup_inputs): x [4,4096,2048] fp32, W [2048,2048] fp32
#define M_DIM 16384
#define K_DIM 2048
#define N_DIM 2048

static const long long NELEM = (long long)M_DIM * (long long)K_DIM;

// Scratch (no alloc allowed)
__device__ __half g_xsp_c[M_DIM * K_DIM / 2];          // compressed 2:4 A (32 MB)
// metadata, fm-vectorized layout:
// u16 idx = mcta*16384 + kt*1024 + g*512 + s*128 + eQ*64 + gr*8 + fm*2 + hi
// (mcta=row>>7, g=(row>>6)&1, fm=(row>>4)&3, hi=(row>>3)&1, gr=row&7;
//  kt=c>>3, s=(c>>1)&3, eQ=c&1; c = k16 chunk index 0..127)
__device__ uint16_t g_meta[M_DIM * K_DIM / 16];        // 4 MB
__device__ __half g_wh[N_DIM * K_DIM];                 // W in fp16 (8 MB)
__device__ double g_sums[4];

// ---------------------------------------------------------------------------
// Kernel 1 (merged): blocks [0,1024): 2:4 prune over a 64-row x 32-chunk tile
// with SMEM-staged, coalesced metadata writeout + moments.
// blocks [1024,2048): convert W to fp16.
// ---------------------------------------------------------------------------
#define PRUNE_BLOCKS 1024
#define WCONV_BLOCKS 1024

__global__ void prep_kernel(const float* __restrict__ x, const float* __restrict__ W) {
    if (blockIdx.x >= PRUNE_BLOCKS) {
        // ---- W conversion branch ----
        const int bid = blockIdx.x - PRUNE_BLOCKS;
        const int nq = N_DIM * K_DIM / 4;                 // 1048576 float4
        __half2* y = (__half2*)g_wh;
        for (int i = bid * blockDim.x + threadIdx.x; i < nq;
             i += WCONV_BLOCKS * blockDim.x) {
            float4 w4 = ((const float4*)W)[i];
            y[2 * i]     = __floats2half2_rn(w4.x, w4.y);
            y[2 * i + 1] = __floats2half2_rn(w4.z, w4.w);
        }
        return;
    }

    // ---- prune branch: block tile = 64 rows x 32 chunks (4 kt groups) ------
    __shared__ uint16_t smeta[2048];                      // 4 KB staged metadata
    __shared__ float red[4][8];

    const int t = threadIdx.x;
    const int w = t >> 5;                                 // warp = row within octet
    const int cl = t & 31;                                // chunk_local 0..31
    const int blk_m = blockIdx.x >> 2;                    // 64-row stripe 0..255
    const int cq = blockIdx.x & 3;                        // chunk quad 0..3
    const int row0 = blk_m << 6;
    const int c0 = cq << 5;
    const int c = c0 + cl;

    // smem staging base for this thread's column position (row part added per i)
    const uint32_t locBase = (uint32_t)(((cl >> 3) << 9) + (((cl >> 1) & 3) << 7) +
                                        ((cl & 1) << 6) + (w << 3));

    float s0 = 0.f, s1 = 0.f, s2 = 0.f, s3 = 0.f;

#pragma unroll
    for (int i = 0; i < 8; i++) {
        const int row = row0 + w + i * 8;
        const float4* xp = (const float4*)x + ((size_t)row * 512 + c * 4);
        uint32_t packed[4];
        uint32_t meta = 0;
#pragma unroll
        for (int g = 0; g < 4; g++) {
            float4 v = xp[g];
            float e[4] = {v.x, v.y, v.z, v.w};
            float a[4] = {fabsf(v.x), fabsf(v.y), fabsf(v.z), fabsf(v.w)};
            int k0 = -1, k1 = -1;
#pragma unroll
            for (int ii = 0; ii < 4; ii++) {
                int beats = 0;
#pragma unroll
                for (int j = 0; j < 4; j++) {
                    if (j == ii) continue;
                    beats += (a[j] > a[ii]) || (a[j] == a[ii] && j < ii);
                }
                if (beats < 2) { if (k0 < 0) k0 = ii; else k1 = ii; }
            }
            const float v0 = e[k0], v1 = e[k1];
            s0 += e[0] + e[1] + e[2] + e[3];
            s1 += e[0]*e[0] + e[1]*e[1] + e[2]*e[2] + e[3]*e[3];
            s2 += v0 + v1;
            s3 += v0 * v0 + v1 * v1;
            __half2 h = __floats2half2_rn(v0, v1);
            packed[g] = *(uint32_t*)&h;
            meta |= (uint32_t)(k0 | (k1 << 2)) << (4 * g);
        }
        ((uint4*)g_xsp_c)[(size_t)row * 128 + c] =
            make_uint4(packed[0], packed[1], packed[2], packed[3]);
        // row_local = w + 8i  =>  gr = w, hi = i&1, fm = (i>>1)&3
        smeta[locBase + (uint32_t)((((i >> 1) & 3) << 1) + (i & 1))] = (uint16_t)meta;
    }

    // ---- moment reduction ----------------------------------------------------
#pragma unroll
    for (int off = 16; off > 0; off >>= 1) {
        s0 += __shfl_down_sync(0xffffffffu, s0, off);
        s1 += __shfl_down_sync(0xffffffffu, s1, off);
        s2 += __shfl_down_sync(0xffffffffu, s2, off);
        s3 += __shfl_down_sync(0xffffffffu, s3, off);
    }
    const int lane = t & 31;
    if (lane == 0) {
        red[0][w] = s0; red[1][w] = s1; red[2][w] = s2; red[3][w] = s3;
    }
    __syncthreads();                    // also orders smeta for the writeout
    if (t == 0) {
        float t0 = 0.f, t1 = 0.f, t2 = 0.f, t3 = 0.f;
        for (int i = 0; i < 8; i++) {
            t0 += red[0][i]; t1 += red[1][i]; t2 += red[2][i]; t3 += red[3][i];
        }
        atomicAdd(&g_sums[0], (double)t0);
        atomicAdd(&g_sums[1], (double)t1);
        atomicAdd(&g_sums[2], (double)t2);
        atomicAdd(&g_sums[3], (double)t3);
    }

    // ---- coalesced metadata writeout: 256 threads x 16B ----------------------
    {
        const int mcta = blk_m >> 1;
        const int gsel = blk_m & 1;
        const uint32_t base0 = (uint32_t)(mcta * 16384 + (cq * 4) * 1024 + gsel * 512);
        const uint32_t gidx = base0 + (uint32_t)((t >> 6) * 1024) +
                              (uint32_t)((t & 63) * 8);
        *(uint4*)(g_meta + gidx) = *(const uint4*)(smeta + t * 8);
    }
}

// ---------------------------------------------------------------------------
// Kernel 2: sparse fp16 GEMM  out[m][n] = v * sum_k x_sp[m][k] * W[n][k]
// mma.sp::ordered_metadata.m16n8k32. BM=BN=128, BKS=128 per K-tile,
// double-buffered cp.async, 8 warps (2x4), warp tile 64x32.
// Lean loader (base+immediate). Metadata: one LDS.128 per s-step.
// ---------------------------------------------------------------------------
#define BM 128
#define BN 128
#define BKS 128                        // source K per tile
#define NITER (K_DIM / BKS)            // 16

#define A_STG_B (BM * 128)             // compressed A: 128B/row -> 16 KB
#define B_STG_B (BN * 256)             // dense B: 256B/row -> 32 KB
#define M_STG_B 2048                   // meta: 2 KB contiguous per ktile
#define STG_B (A_STG_B + B_STG_B + M_STG_B)
#define SMEM_DYN (2 * STG_B + 1024)

static __device__ __forceinline__ uint32_t smem_u32(const void* p) {
    uint32_t a;
    asm("{ .reg .u64 t; cvta.to.shared.u64 t, %1; cvt.u32.u64 %0, t; }" : "=r"(a) : "l"(p));
    return a;
}

#define CP_ASYNC16(dst, src) \
    asm volatile("cp.async.cg.shared.global [%0], [%1], 16;" :: "r"(dst), "l"(src) : "memory")
#define CP_COMMIT() asm volatile("cp.async.commit_group;" ::: "memory")
#define CP_WAIT1()  asm volatile("cp.async.wait_group 1;" ::: "memory")
#define CP_WAIT0()  asm volatile("cp.async.wait_group 0;" ::: "memory")

#define LDSM_X4(r0, r1, r2, r3, addr) \
    asm volatile("ldmatrix.sync.aligned.m8n8.x4.shared.b16 {%0,%1,%2,%3}, [%4];" \
        : "=r"(r0), "=r"(r1), "=r"(r2), "=r"(r3) : "r"(addr))

static __device__ __forceinline__ void mma_sp(
    float* c, const uint32_t* a,
    uint32_t b0, uint32_t b1, uint32_t b2, uint32_t b3, uint32_t e) {
    asm volatile(
        "mma.sp::ordered_metadata.sync.aligned.m16n8k32.row.col.f32.f16.f16.f32 "
        "{%0,%1,%2,%3}, {%4,%5,%6,%7}, {%8,%9,%10,%11}, {%0,%1,%2,%3}, %12, 0x0;"
        : "+f"(c[0]), "+f"(c[1]), "+f"(c[2]), "+f"(c[3])
        : "r"(a[0]), "r"(a[1]), "r"(a[2]), "r"(a[3]),
          "r"(b0), "r"(b1), "r"(b2), "r"(b3), "r"(e));
}

__global__ __launch_bounds__(256, 2)
void gemm_sp_kernel(float* __restrict__ out) {
    extern __shared__ char smem[];

    const int tid = threadIdx.x;
    const int wid = tid >> 5;
    const int lane = tid & 31;
    const int bm = blockIdx.y * BM;
    const int bn = blockIdx.x * BN;

    const uint32_t tile_base = (smem_u32(smem) + 1023u) & ~1023u;

    // ---- loader bases (chunk index only shifts row by multiples of 8, so
    //      row&7, c, and the swizzle XOR are all chunk-invariant) ------------
    const char* aSrc = (const char*)g_xsp_c + (size_t)bm * 2048 +
                       (size_t)(tid >> 3) * 2048 + (tid & 7) * 16;
    const uint32_t aDst = (uint32_t)((tid >> 3) * 128 +
                          (((tid & 7) ^ ((tid >> 3) & 7)) << 4));
    const char* bSrc = (const char*)g_wh + (size_t)bn * 4096 +
                       (size_t)(tid >> 4) * 4096 + (tid & 15) * 16;
    const uint32_t bDst = (uint32_t)(A_STG_B + (tid >> 4) * 256 +
                          ((((tid & 15) & 8) | (((tid & 15) ^ (tid >> 4)) & 7)) << 4));
    const char* mSrc = (const char*)g_meta + (size_t)(bm >> 7) * 32768 + tid * 16;
    const uint32_t mDst = (uint32_t)(A_STG_B + B_STG_B + tid * 16);

    auto load_stage = [&](int buf, int kt) {
        const uint32_t base = tile_base + buf * STG_B;
        const int ka = kt * 128;                // A byte offset along K
        const int kb = kt * 256;                // B byte offset along K
#pragma unroll
        for (int i = 0; i < 4; i++)
            CP_ASYNC16(base + aDst + i * 4096, aSrc + ka + i * 65536);
#pragma unroll
        for (int i = 0; i < 8; i++)
            CP_ASYNC16(base + bDst + i * 4096, bSrc + kb + i * 65536);
        if (tid < 128)
            CP_ASYNC16(base + mDst, mSrc + kt * 2048);
    };

    load_stage(0, 0);
    CP_COMMIT();

    const int mw = (wid >> 2) * 64;     // warp M offset
    const int nw = (wid & 3) * 32;      // warp N offset
    const int gr = lane >> 2;
    const int tg = lane & 3;

    float acc[4][4][4];
#pragma unroll
    for (int i = 0; i < 4; i++)
#pragma unroll
        for (int j = 0; j < 4; j++)
#pragma unroll
            for (int q = 0; q < 4; q++) acc[i][j][q] = 0.f;

    // precomputed fragment addressing
    const int aRow = lane & 15;                 // within 16-row block
    const int aKc = lane >> 4;                  // chunk parity
    const int bRow = ((lane >> 4) << 3) + (lane & 7);
    const int bKc = (lane >> 3) & 1;
    const int eQ = lane & 1;                    // metadata chunk parity
    const uint32_t mInv = (uint32_t)(A_STG_B + B_STG_B +
                                     (mw >> 6) * 1024 + eQ * 128 + gr * 16);

    for (int kt = 0; kt < NITER; kt++) {
        if (kt + 1 < NITER) {
            load_stage((kt + 1) & 1, kt + 1);
            CP_COMMIT();
            CP_WAIT1();
        } else {
            CP_WAIT0();
        }
        __syncthreads();

        const uint32_t sA = tile_base + (kt & 1) * STG_B;
        const uint32_t sB = sA + A_STG_B;
        const uint32_t mAddr0 = sA + mInv - (uint32_t)0;  // stage base + meta inv

#pragma unroll
        for (int s = 0; s < 4; s++) {           // 4 x k32 steps (compressed k16)
            uint32_t a[4][4];
#pragma unroll
            for (int fm = 0; fm < 4; fm++) {
                const int row = mw + fm * 16 + aRow;
                const int c = s * 2 + aKc;
                LDSM_X4(a[fm][0], a[fm][1], a[fm][2], a[fm][3],
                        sA + row * 128 + ((uint32_t)(c ^ (row & 7)) << 4));
            }
            uint32_t bf[2][2][4];               // [pr][khalf][reg]
#pragma unroll
            for (int pr = 0; pr < 2; pr++)
#pragma unroll
                for (int h = 0; h < 2; h++) {
                    const int row = nw + pr * 16 + bRow;
                    const int c = s * 4 + h * 2 + bKc;
                    const uint32_t swc = (uint32_t)((c & 8) | ((c ^ row) & 7));
                    LDSM_X4(bf[pr][h][0], bf[pr][h][1], bf[pr][h][2], bf[pr][h][3],
                            sB + row * 256 + (swc << 4));
                }
            // metadata: one LDS.128 -> ee[fm=0..3] for this s-step
            uint32_t ee[4];
            asm volatile("ld.shared.v4.u32 {%0,%1,%2,%3}, [%4];"
                : "=r"(ee[0]), "=r"(ee[1]), "=r"(ee[2]), "=r"(ee[3])
                : "r"(mAddr0 + (uint32_t)(s * 256)));
#pragma unroll
            for (int fm = 0; fm < 4; fm++)
#pragma unroll
                for (int fn = 0; fn < 4; fn++)
                    mma_sp(acc[fm][fn], a[fm],
                           bf[fn >> 1][0][(fn & 1) * 2], bf[fn >> 1][0][(fn & 1) * 2 + 1],
                           bf[fn >> 1][1][(fn & 1) * 2], bf[fn >> 1][1][(fn & 1) * 2 + 1],
                           ee[fm]);
        }
        __syncthreads();
    }

    // ---- epilogue: compute v from moments, scale + store --------------------
    const double n = (double)NELEM;
    const double var_x  = (g_sums[1] - g_sums[0] * g_sums[0] / n) / (n - 1.0);
    double var_sp = (g_sums[3] - g_sums[2] * g_sums[2] / n) / (n - 1.0);
    if (var_sp < 1e-9) var_sp = 1e-9;
    const float v = (float)sqrt(var_x / var_sp);

#pragma unroll
    for (int fm = 0; fm < 4; fm++) {
        const int r0 = bm + mw + fm * 16 + gr;
        const int r1 = r0 + 8;
#pragma unroll
        for (int fn = 0; fn < 4; fn++) {
            const int c = bn + nw + fn * 8 + tg * 2;
            *(float2*)&out[(size_t)r0 * N_DIM + c] =
                make_float2(v * acc[fm][fn][0], v * acc[fm][fn][1]);
            *(float2*)&out[(size_t)r1 * N_DIM + c] =
                make_float2(v * acc[fm][fn][2], v * acc[fm][fn][3]);
        }
    }
}

// ---------------------------------------------------------------------------
// Entry point
// ---------------------------------------------------------------------------
extern "C" void kernel_launch(void* const* d_in, const int* in_sizes, int n_in,
                              void* d_out, int out_size) {
    const float* x = (const float*)d_in[0];
    const float* w = (const float*)d_in[1];
    float* out = (float*)d_out;

    // zero the moment accumulators via a graph-capturable memset node
    void* sums_addr = 0;
    cudaGetSymbolAddress(&sums_addr, g_sums);
    cudaMemsetAsync(sums_addr, 0, 4 * sizeof(double));

    prep_kernel<<<PRUNE_BLOCKS + WCONV_BLOCKS, 256>>>(x, w);

    cudaFuncSetAttribute(gemm_sp_kernel,
                         cudaFuncAttributeMaxDynamicSharedMemorySize, SMEM_DYN);
    dim3 grid(N_DIM / BN, M_DIM / BM);
    gemm_sp_kernel<<<grid, 256, SMEM_DYN>>>(out);
}